// round 1
// baseline (speedup 1.0000x reference)
#include <cuda_runtime.h>

// Problem constants
#define BATCH  4
#define SEQ    4096
#define M_TOK  (BATCH * SEQ)   // 16384 tokens
#define EDIM   1024
#define HEADS  16
#define DH     64

// GEMM tiling
#define BM 128
#define BN 128
#define BK 8
#define KTILES (EDIM / BK)     // 128
#define PAD 4
#define LDA (BM + PAD)         // padded smem row to avoid transpose-store bank conflicts

// Scratch for projected Q/K/V (device globals: alloc-free per harness rules)
__device__ float g_q[(size_t)M_TOK * EDIM];
__device__ float g_k[(size_t)M_TOK * EDIM];
__device__ float g_v[(size_t)M_TOK * EDIM];

typedef unsigned long long u64;

// ---- packed f32x2 helpers (Blackwell sm_103a) ----
__device__ __forceinline__ u64 pack2(float lo, float hi) {
    u64 r;
    asm("mov.b64 %0, {%1, %2};" : "=l"(r) : "f"(lo), "f"(hi));
    return r;
}
__device__ __forceinline__ void unpack2(u64 v, float& lo, float& hi) {
    asm("mov.b64 {%0, %1}, %2;" : "=f"(lo), "=f"(hi) : "l"(v));
}
__device__ __forceinline__ void ffma2(u64& d, u64 a, u64 b) {
    // d = a * b + d  (two packed fp32 lanes)
    asm("fma.rn.f32x2 %0, %1, %2, %0;" : "+l"(d) : "l"(a), "l"(b));
}

// ============================================================================
// Fused QKV projection GEMM:  C[m, n] = sum_k X[m, k] * W[n, k] + bias[n]
// X: [16384, 1024] row-major, W: [1024, 1024] row-major (torch Linear W),
// gridDim.z selects (Wq,bq,g_q) / (Wk,bk,g_k) / (Wv,bv,g_v).
// 128x128x8 tile, 256 threads, 8x8 microtile as f32x2 pairs, double-buffered.
// ============================================================================
__global__ __launch_bounds__(256, 2)
void qkv_gemm(const float* __restrict__ X,
              const float* __restrict__ Wq, const float* __restrict__ bq,
              const float* __restrict__ Wk, const float* __restrict__ bk,
              const float* __restrict__ Wv, const float* __restrict__ bv)
{
    const float* W;
    const float* bias;
    float* C;
    if (blockIdx.z == 0)      { W = Wq; bias = bq; C = g_q; }
    else if (blockIdx.z == 1) { W = Wk; bias = bk; C = g_k; }
    else                      { W = Wv; bias = bv; C = g_v; }

    __shared__ float As[2][BK][LDA];
    __shared__ float Bs[2][BK][LDA];

    const int tid  = threadIdx.x;
    const int row0 = blockIdx.y * BM;
    const int col0 = blockIdx.x * BN;

    // global-load mapping: each thread loads one float4 of the 128x8 tile
    const int lr = tid >> 1;          // 0..127 (tile row)
    const int lc = (tid & 1) << 2;    // 0 or 4 (k offset)

    const float* Ap = X + (size_t)(row0 + lr) * EDIM + lc;
    const float* Bp = W + (size_t)(col0 + lr) * EDIM + lc;

    // prologue: stage k-tile 0 (transposed: smem is [k][row])
    {
        float4 a = *(const float4*)Ap;
        float4 b = *(const float4*)Bp;
        As[0][lc + 0][lr] = a.x; As[0][lc + 1][lr] = a.y;
        As[0][lc + 2][lr] = a.z; As[0][lc + 3][lr] = a.w;
        Bs[0][lc + 0][lr] = b.x; Bs[0][lc + 1][lr] = b.y;
        Bs[0][lc + 2][lr] = b.z; Bs[0][lc + 3][lr] = b.w;
    }
    __syncthreads();

    const int ty = tid >> 4;   // 0..15 -> output rows ty*8..ty*8+7
    const int tx = tid & 15;   // 0..15 -> output cols tx*8..tx*8+7

    u64 acc[8][4];             // 8 rows x 4 f32x2 column-pairs
    #pragma unroll
    for (int i = 0; i < 8; i++)
        #pragma unroll
        for (int j = 0; j < 4; j++) acc[i][j] = 0ull;

    int buf = 0;
    for (int kt = 0; kt < KTILES; kt++) {
        float4 an, bn;
        const bool has_next = (kt + 1 < KTILES);
        if (has_next) {  // prefetch next k-tile into registers (overlaps compute)
            an = *(const float4*)(Ap + (kt + 1) * BK);
            bn = *(const float4*)(Bp + (kt + 1) * BK);
        }

        #pragma unroll
        for (int kk = 0; kk < BK; kk++) {
            float4 a0 = *(const float4*)&As[buf][kk][ty * 8];
            float4 a1 = *(const float4*)&As[buf][kk][ty * 8 + 4];
            // b column-pairs: two consecutive floats in smem ARE an f32x2 register pair
            ulonglong2 bb0 = *(const ulonglong2*)&Bs[buf][kk][tx * 8];
            ulonglong2 bb1 = *(const ulonglong2*)&Bs[buf][kk][tx * 8 + 4];
            u64 bp0 = bb0.x, bp1 = bb0.y, bp2 = bb1.x, bp3 = bb1.y;
            float av[8] = {a0.x, a0.y, a0.z, a0.w, a1.x, a1.y, a1.z, a1.w};
            #pragma unroll
            for (int i = 0; i < 8; i++) {
                u64 as2 = pack2(av[i], av[i]);   // splat row value
                ffma2(acc[i][0], as2, bp0);
                ffma2(acc[i][1], as2, bp1);
                ffma2(acc[i][2], as2, bp2);
                ffma2(acc[i][3], as2, bp3);
            }
        }

        if (has_next) {
            const int nb = buf ^ 1;
            As[nb][lc + 0][lr] = an.x; As[nb][lc + 1][lr] = an.y;
            As[nb][lc + 2][lr] = an.z; As[nb][lc + 3][lr] = an.w;
            Bs[nb][lc + 0][lr] = bn.x; Bs[nb][lc + 1][lr] = bn.y;
            Bs[nb][lc + 2][lr] = bn.z; Bs[nb][lc + 3][lr] = bn.w;
        }
        __syncthreads();
        buf ^= 1;
    }

    // epilogue: unpack, add bias, vectorized store
    const int ccol = col0 + tx * 8;
    float bcol[8];
    #pragma unroll
    for (int j = 0; j < 8; j++) bcol[j] = bias[ccol + j];

    #pragma unroll
    for (int i = 0; i < 8; i++) {
        const int r = row0 + ty * 8 + i;
        float o[8];
        #pragma unroll
        for (int j = 0; j < 4; j++) unpack2(acc[i][j], o[2 * j], o[2 * j + 1]);
        float4 v0 = make_float4(o[0] + bcol[0], o[1] + bcol[1],
                                o[2] + bcol[2], o[3] + bcol[3]);
        float4 v1 = make_float4(o[4] + bcol[4], o[5] + bcol[5],
                                o[6] + bcol[6], o[7] + bcol[7]);
        *(float4*)&C[(size_t)r * EDIM + ccol]     = v0;
        *(float4*)&C[(size_t)r * EDIM + ccol + 4] = v1;
    }
}

// ============================================================================
// Per-token head-head attention.
// scores[h,g] = (q[h] . k[g]) * mask[h,g]   (mask BEFORE softmax; zeros still
// contribute exp(0-m) to the softmax — must match reference exactly)
// out[h] = sum_g softmax(scores)[h,g] * v[g]
// One 64-thread block handles 4 tokens; thread = (token, head).
// ============================================================================
__global__ __launch_bounds__(64)
void attn_kernel(const float* __restrict__ mask, float* __restrict__ out)
{
    __shared__ float ks[4 * HEADS * DH];   // 16 KB
    __shared__ float vs[4 * HEADS * DH];   // 16 KB
    __shared__ float ms[HEADS * HEADS];    // 1 KB

    const int tid = threadIdx.x;
    const size_t tok0 = (size_t)blockIdx.x * 4;

    for (int i = tid; i < HEADS * HEADS; i += 64) ms[i] = mask[i];

    const float4* kg = (const float4*)(g_k + tok0 * EDIM);
    const float4* vg = (const float4*)(g_v + tok0 * EDIM);
    float4* ks4 = (float4*)ks;
    float4* vs4 = (float4*)vs;
    #pragma unroll
    for (int i = 0; i < 16; i++) {   // 4 tokens * 1024 floats = 1024 float4 each
        ks4[tid + i * 64] = kg[tid + i * 64];
        vs4[tid + i * 64] = vg[tid + i * 64];
    }
    __syncthreads();

    const int t = tid >> 4;    // token within block (0..3)
    const int h = tid & 15;    // head

    // q row into registers
    float4 qv[16];
    const float4* qp = (const float4*)(g_q + (tok0 + t) * EDIM + h * DH);
    #pragma unroll
    for (int i = 0; i < 16; i++) qv[i] = qp[i];

    // scores
    float s[16];
    #pragma unroll
    for (int g = 0; g < 16; g++) {
        const float4* kr = (const float4*)(ks + (t * HEADS + g) * DH);
        float ax = 0.f, ay = 0.f, az = 0.f, aw = 0.f;
        #pragma unroll
        for (int i = 0; i < 16; i++) {
            float4 kv = kr[i];
            ax += qv[i].x * kv.x; ay += qv[i].y * kv.y;
            az += qv[i].z * kv.z; aw += qv[i].w * kv.w;
        }
        s[g] = ((ax + ay) + (az + aw)) * ms[h * HEADS + g];
    }

    // softmax over g (includes masked-to-zero entries, like the reference)
    float m = s[0];
    #pragma unroll
    for (int g = 1; g < 16; g++) m = fmaxf(m, s[g]);
    float denom = 0.f;
    #pragma unroll
    for (int g = 0; g < 16; g++) { s[g] = expf(s[g] - m); denom += s[g]; }
    const float inv = 1.f / denom;

    // out = attn @ v
    float4 o[16];
    #pragma unroll
    for (int i = 0; i < 16; i++) o[i] = make_float4(0.f, 0.f, 0.f, 0.f);
    #pragma unroll
    for (int g = 0; g < 16; g++) {
        const float p = s[g] * inv;
        const float4* vr = (const float4*)(vs + (t * HEADS + g) * DH);
        #pragma unroll
        for (int i = 0; i < 16; i++) {
            float4 vv = vr[i];
            o[i].x += p * vv.x; o[i].y += p * vv.y;
            o[i].z += p * vv.z; o[i].w += p * vv.w;
        }
    }

    float4* op = (float4*)(out + (tok0 + t) * EDIM + h * DH);
    #pragma unroll
    for (int i = 0; i < 16; i++) op[i] = o[i];
}

// ============================================================================
// Launch. Inputs (metadata order): x, sparsity_pattern, Wq, bq, Wk, bk, Wv, bv
// ============================================================================
extern "C" void kernel_launch(void* const* d_in, const int* in_sizes, int n_in,
                              void* d_out, int out_size)
{
    (void)in_sizes; (void)n_in; (void)out_size;
    const float* x  = (const float*)d_in[0];
    const float* sp = (const float*)d_in[1];
    const float* Wq = (const float*)d_in[2];
    const float* bq = (const float*)d_in[3];
    const float* Wk = (const float*)d_in[4];
    const float* bk = (const float*)d_in[5];
    const float* Wv = (const float*)d_in[6];
    const float* bv = (const float*)d_in[7];
    float* out = (float*)d_out;

    dim3 grid(EDIM / BN, M_TOK / BM, 3);   // 8 x 128 x 3
    qkv_gemm<<<grid, 256>>>(x, Wq, bq, Wk, bk, Wv, bv);
    attn_kernel<<<M_TOK / 4, 64>>>(sp, out);
}

// round 3
// speedup vs baseline: 2.3687x; 2.3687x over previous
#include <cuda_runtime.h>
#include <cuda_bf16.h>
#include <cstdint>

// Problem constants
#define BATCH  4
#define SEQ    4096
#define M_TOK  (BATCH * SEQ)   // 16384 tokens
#define EDIM   1024
#define HEADS  16
#define DH     64

#define KTOT   3072            // packed K = 3*EDIM (hi|hi|lo)
#define NTOT   3072            // packed N = q|k|v

typedef unsigned long long u64;
typedef unsigned int       u32;

// ---------------------------------------------------------------------------
// Device scratch (alloc-free per harness rules)
// ---------------------------------------------------------------------------
__device__ __nv_bfloat16 g_ap[(size_t)M_TOK * KTOT];   // [Xhi | Xhi | Xlo]
__device__ __nv_bfloat16 g_bp[(size_t)NTOT * KTOT];    // rows: [Whi | Wlo | Whi]
__device__ float         g_bias[NTOT];
__device__ float         g_qkv[(size_t)M_TOK * NTOT];  // q | k | v per row

// ---------------------------------------------------------------------------
// PTX helpers (all compute_103-legal: cp.async / ldmatrix / mma.sync)
// ---------------------------------------------------------------------------
__device__ __forceinline__ u32 s2u(const void* p) {
    u32 a;
    asm("{ .reg .u64 t; cvta.to.shared.u64 t, %1; cvt.u32.u64 %0, t; }"
        : "=r"(a) : "l"(p));
    return a;
}
__device__ __forceinline__ void cpa16(u32 dst, const void* src) {
    asm volatile("cp.async.cg.shared.global [%0], [%1], 16;"
                 :: "r"(dst), "l"(src) : "memory");
}
#define CPA_COMMIT() asm volatile("cp.async.commit_group;" ::: "memory")
#define CPA_WAIT1()  asm volatile("cp.async.wait_group 1;" ::: "memory")
#define CPA_WAIT0()  asm volatile("cp.async.wait_group 0;" ::: "memory")

__device__ __forceinline__ void ldsm4(u32* r, u32 addr) {
    asm volatile("ldmatrix.sync.aligned.m8n8.x4.shared.b16 {%0,%1,%2,%3}, [%4];"
                 : "=r"(r[0]), "=r"(r[1]), "=r"(r[2]), "=r"(r[3]) : "r"(addr));
}
__device__ __forceinline__ void mma_bf16(float* d, const u32* a, const u32* b) {
    asm volatile(
        "mma.sync.aligned.m16n8k16.row.col.f32.bf16.bf16.f32 "
        "{%0,%1,%2,%3}, {%4,%5,%6,%7}, {%8,%9}, {%0,%1,%2,%3};"
        : "+f"(d[0]), "+f"(d[1]), "+f"(d[2]), "+f"(d[3])
        : "r"(a[0]), "r"(a[1]), "r"(a[2]), "r"(a[3]), "r"(b[0]), "r"(b[1]));
}

// ---------------------------------------------------------------------------
// Pack kernels: hi/lo bf16 split into the K-concat layout
// ---------------------------------------------------------------------------
__device__ __forceinline__ void split4(float4 v, __nv_bfloat162& h01, __nv_bfloat162& h23,
                                       __nv_bfloat162& l01, __nv_bfloat162& l23) {
    __nv_bfloat16 h0 = __float2bfloat16(v.x);
    __nv_bfloat16 h1 = __float2bfloat16(v.y);
    __nv_bfloat16 h2 = __float2bfloat16(v.z);
    __nv_bfloat16 h3 = __float2bfloat16(v.w);
    h01 = __halves2bfloat162(h0, h1);
    h23 = __halves2bfloat162(h2, h3);
    l01 = __halves2bfloat162(__float2bfloat16(v.x - __bfloat162float(h0)),
                             __float2bfloat16(v.y - __bfloat162float(h1)));
    l23 = __halves2bfloat162(__float2bfloat16(v.z - __bfloat162float(h2)),
                             __float2bfloat16(v.w - __bfloat162float(h3)));
}

__global__ void pack_x(const float4* __restrict__ x) {
    int i = blockIdx.x * blockDim.x + threadIdx.x;
    const int n4 = M_TOK * EDIM / 4;
    const int stride = gridDim.x * blockDim.x;
    __nv_bfloat162* out = (__nv_bfloat162*)g_ap;
    for (; i < n4; i += stride) {
        float4 v = x[i];
        __nv_bfloat162 h01, h23, l01, l23;
        split4(v, h01, h23, l01, l23);
        const int e0  = i * 4;
        const int row = e0 >> 10;
        const int col = e0 & 1023;
        const size_t base = ((size_t)row * KTOT + col) >> 1;
        out[base]           = h01;  out[base + 1]           = h23;   // slot hi
        out[base + 512]     = h01;  out[base + 513]         = h23;   // slot hi
        out[base + 1024]    = l01;  out[base + 1025]        = l23;   // slot lo
    }
}

__global__ void pack_w(const float4* __restrict__ Wq,
                       const float4* __restrict__ Wk,
                       const float4* __restrict__ Wv) {
    int i = blockIdx.x * blockDim.x + threadIdx.x;
    const int per = EDIM * EDIM / 4;
    const int n4 = 3 * per;
    const int stride = gridDim.x * blockDim.x;
    __nv_bfloat162* out = (__nv_bfloat162*)g_bp;
    for (; i < n4; i += stride) {
        const int z = i / per;
        const int r = i - z * per;
        float4 v = (z == 0 ? Wq : z == 1 ? Wk : Wv)[r];
        __nv_bfloat162 h01, h23, l01, l23;
        split4(v, h01, h23, l01, l23);
        const int e0  = r * 4;
        const int row = e0 >> 10;           // weight output row c
        const int col = e0 & 1023;
        const size_t base = ((size_t)(z * EDIM + row) * KTOT + col) >> 1;
        out[base]        = h01;  out[base + 1]    = h23;   // hi
        out[base + 512]  = l01;  out[base + 513]  = l23;   // lo
        out[base + 1024] = h01;  out[base + 1025] = h23;   // hi
    }
}

__global__ void pack_bias(const float* __restrict__ bq,
                          const float* __restrict__ bk,
                          const float* __restrict__ bv) {
    int i = blockIdx.x * blockDim.x + threadIdx.x;
    if (i < NTOT) {
        const int z = i >> 10;
        g_bias[i] = (z == 0 ? bq : z == 1 ? bk : bv)[i & 1023];
    }
}

// ---------------------------------------------------------------------------
// bf16 mma.sync GEMM: C[m,n] = sum_k Apack[m,k]*Bpack[n,k] + bias[n]
// Tile 128x256x64, 512 threads (16 warps 4Mx4N), 3-stage cp.async pipeline.
// ---------------------------------------------------------------------------
#define GBM 128
#define GBN 256
#define GBK 64
#define NSTG 3
#define KIT (KTOT / GBK)          // 48
#define A_STG 16384               // 128 rows * 128B
#define B_STG 32768               // 256 rows * 128B
#define STG_BYTES (A_STG + B_STG) // 49152
#define SMEM_GEMM (NSTG * STG_BYTES + 128)

// swizzled smem byte offset for (row, 16B-chunk c) in a 128B-row tile
__device__ __forceinline__ u32 swz(int row, int c) {
    return (u32)(row * 128 + ((c ^ (row & 7)) << 4));
}

__device__ __forceinline__ void load_stage(u32 smb, int s, int kt,
                                           int row0, int col0, int tid) {
    const u32 aB = smb + s * STG_BYTES;
    const u32 bB = aB + A_STG;
    const __nv_bfloat16* Ag = g_ap;
    const __nv_bfloat16* Bg = g_bp;
    // A: 1024 chunks (128 rows x 8), 2 per thread
    #pragma unroll
    for (int j = 0; j < 2; j++) {
        const int ci = tid + j * 512;
        const int r = ci >> 3, c = ci & 7;
        cpa16(aB + swz(r, c),
              Ag + (size_t)(row0 + r) * KTOT + kt * GBK + c * 8);
    }
    // B: 2048 chunks (256 rows x 8), 4 per thread
    #pragma unroll
    for (int j = 0; j < 4; j++) {
        const int ci = tid + j * 512;
        const int r = ci >> 3, c = ci & 7;
        cpa16(bB + swz(r, c),
              Bg + (size_t)(col0 + r) * KTOT + kt * GBK + c * 8);
    }
}

__global__ void __launch_bounds__(512, 1)
qkv_mma_gemm()
{
    extern __shared__ char smraw[];
    const u32 smb = (s2u(smraw) + 127u) & ~127u;

    const int tid  = threadIdx.x;
    const int wid  = tid >> 5;
    const int lane = tid & 31;
    const int wm   = wid & 3;          // warp M index (0..3) -> 32 rows
    const int wn   = wid >> 2;         // warp N index (0..3) -> 64 cols
    const int row0 = blockIdx.y * GBM;
    const int col0 = blockIdx.x * GBN;

    float acc[2][8][4];
    #pragma unroll
    for (int i = 0; i < 2; i++)
        #pragma unroll
        for (int j = 0; j < 8; j++)
            #pragma unroll
            for (int k = 0; k < 4; k++) acc[i][j][k] = 0.f;

    // prologue: stages 0,1
    load_stage(smb, 0, 0, row0, col0, tid);
    CPA_COMMIT();
    load_stage(smb, 1, 1, row0, col0, tid);
    CPA_COMMIT();

    for (int kt = 0; kt < KIT; kt++) {
        CPA_WAIT1();
        __syncthreads();

        const int s = kt % NSTG;
        const u32 aB = smb + s * STG_BYTES;
        const u32 bB = aB + A_STG;

        #pragma unroll
        for (int kk = 0; kk < 4; kk++) {
            u32 ra[2][4];
            #pragma unroll
            for (int mi = 0; mi < 2; mi++) {
                const int r = wm * 32 + mi * 16 + (lane & 15);
                const int c = kk * 2 + (lane >> 4);
                ldsm4(ra[mi], aB + swz(r, c));
            }
            u32 rb[4][4];
            #pragma unroll
            for (int ni = 0; ni < 4; ni++) {
                const int r = wn * 64 + ni * 16 + (lane & 7) + ((lane >> 4) << 3);
                const int c = kk * 2 + ((lane >> 3) & 1);
                ldsm4(rb[ni], bB + swz(r, c));
            }
            #pragma unroll
            for (int mi = 0; mi < 2; mi++)
                #pragma unroll
                for (int n8 = 0; n8 < 8; n8++)
                    mma_bf16(acc[mi][n8], ra[mi], &rb[n8 >> 1][(n8 & 1) * 2]);
        }

        __syncthreads();
        if (kt + 2 < KIT)
            load_stage(smb, (kt + 2) % NSTG, kt + 2, row0, col0, tid);
        CPA_COMMIT();
    }

    // epilogue: add bias, write g_qkv
    const int rbase = row0 + wm * 32;
    const int cbase = col0 + wn * 64;
    #pragma unroll
    for (int mi = 0; mi < 2; mi++) {
        const int r = rbase + mi * 16 + (lane >> 2);
        #pragma unroll
        for (int n8 = 0; n8 < 8; n8++) {
            const int c = cbase + n8 * 8 + (lane & 3) * 2;
            const float b0 = g_bias[c], b1 = g_bias[c + 1];
            float2 v0 = make_float2(acc[mi][n8][0] + b0, acc[mi][n8][1] + b1);
            float2 v1 = make_float2(acc[mi][n8][2] + b0, acc[mi][n8][3] + b1);
            *(float2*)&g_qkv[(size_t)r * NTOT + c]       = v0;
            *(float2*)&g_qkv[(size_t)(r + 8) * NTOT + c] = v1;
        }
    }
}

// ---------------------------------------------------------------------------
// Per-token head-head attention (reads g_qkv; mask-before-softmax semantics)
// ---------------------------------------------------------------------------
__global__ __launch_bounds__(64)
void attn_kernel(const float* __restrict__ mask, float* __restrict__ out)
{
    __shared__ float ks[4 * HEADS * DH];
    __shared__ float vs[4 * HEADS * DH];
    __shared__ float ms[HEADS * HEADS];

    const int tid = threadIdx.x;
    const size_t tok0 = (size_t)blockIdx.x * 4;

    for (int i = tid; i < HEADS * HEADS; i += 64) ms[i] = mask[i];

    float4* ks4 = (float4*)ks;
    float4* vs4 = (float4*)vs;
    #pragma unroll
    for (int tt = 0; tt < 4; tt++) {
        const float4* kg = (const float4*)(g_qkv + (tok0 + tt) * NTOT + EDIM);
        const float4* vg = (const float4*)(g_qkv + (tok0 + tt) * NTOT + 2 * EDIM);
        #pragma unroll
        for (int j = 0; j < 4; j++) {
            const int idx = tid + j * 64;
            ks4[tt * 256 + idx] = kg[idx];
            vs4[tt * 256 + idx] = vg[idx];
        }
    }
    __syncthreads();

    const int t = tid >> 4;
    const int h = tid & 15;

    float4 qv[16];
    const float4* qp = (const float4*)(g_qkv + (tok0 + t) * NTOT + h * DH);
    #pragma unroll
    for (int i = 0; i < 16; i++) qv[i] = qp[i];

    float s[16];
    #pragma unroll
    for (int g = 0; g < 16; g++) {
        const float4* kr = (const float4*)(ks + (t * HEADS + g) * DH);
        float ax = 0.f, ay = 0.f, az = 0.f, aw = 0.f;
        #pragma unroll
        for (int i = 0; i < 16; i++) {
            float4 kv = kr[i];
            ax += qv[i].x * kv.x; ay += qv[i].y * kv.y;
            az += qv[i].z * kv.z; aw += qv[i].w * kv.w;
        }
        s[g] = ((ax + ay) + (az + aw)) * ms[h * HEADS + g];
    }

    float m = s[0];
    #pragma unroll
    for (int g = 1; g < 16; g++) m = fmaxf(m, s[g]);
    float denom = 0.f;
    #pragma unroll
    for (int g = 0; g < 16; g++) { s[g] = expf(s[g] - m); denom += s[g]; }
    const float inv = 1.f / denom;

    float4 o[16];
    #pragma unroll
    for (int i = 0; i < 16; i++) o[i] = make_float4(0.f, 0.f, 0.f, 0.f);
    #pragma unroll
    for (int g = 0; g < 16; g++) {
        const float p = s[g] * inv;
        const float4* vr = (const float4*)(vs + (t * HEADS + g) * DH);
        #pragma unroll
        for (int i = 0; i < 16; i++) {
            float4 vv = vr[i];
            o[i].x += p * vv.x; o[i].y += p * vv.y;
            o[i].z += p * vv.z; o[i].w += p * vv.w;
        }
    }

    float4* op = (float4*)(out + (tok0 + t) * EDIM + h * DH);
    #pragma unroll
    for (int i = 0; i < 16; i++) op[i] = o[i];
}

// ---------------------------------------------------------------------------
// Launch. Inputs: x, sparsity_pattern, Wq, bq, Wk, bk, Wv, bv
// ---------------------------------------------------------------------------
extern "C" void kernel_launch(void* const* d_in, const int* in_sizes, int n_in,
                              void* d_out, int out_size)
{
    (void)in_sizes; (void)n_in; (void)out_size;
    const float* x  = (const float*)d_in[0];
    const float* sp = (const float*)d_in[1];
    const float* Wq = (const float*)d_in[2];
    const float* bq = (const float*)d_in[3];
    const float* Wk = (const float*)d_in[4];
    const float* bk = (const float*)d_in[5];
    const float* Wv = (const float*)d_in[6];
    const float* bv = (const float*)d_in[7];
    float* out = (float*)d_out;

    pack_x<<<4096, 256>>>((const float4*)x);
    pack_w<<<1536, 256>>>((const float4*)Wq, (const float4*)Wk, (const float4*)Wv);
    pack_bias<<<12, 256>>>(bq, bk, bv);

    cudaFuncSetAttribute(qkv_mma_gemm,
                         cudaFuncAttributeMaxDynamicSharedMemorySize, SMEM_GEMM);
    dim3 grid(NTOT / GBN, M_TOK / GBM);    // (12, 128)
    qkv_mma_gemm<<<grid, 512, SMEM_GEMM>>>();

    attn_kernel<<<M_TOK / 4, 64>>>(sp, out);
}

// round 4
// speedup vs baseline: 2.4831x; 1.0483x over previous
#include <cuda_runtime.h>
#include <cuda_bf16.h>
#include <cstdint>

// Problem constants
#define BATCH  4
#define SEQ    4096
#define M_TOK  (BATCH * SEQ)   // 16384 tokens
#define EDIM   1024
#define HEADS  16
#define DH     64

#define KTOT   3072            // packed K = 3*EDIM (hi|hi|lo)
#define NTOT   3072            // packed N = q|k|v

typedef unsigned long long u64;
typedef unsigned int       u32;

// ---------------------------------------------------------------------------
// Device scratch (alloc-free per harness rules)
// ---------------------------------------------------------------------------
__device__ __nv_bfloat16 g_ap[(size_t)M_TOK * KTOT];   // [Xhi | Xhi | Xlo]
__device__ __nv_bfloat16 g_bp[(size_t)NTOT * KTOT];    // rows: [Whi | Wlo | Whi]
__device__ float         g_bias[NTOT];
__device__ float         g_qkv[(size_t)M_TOK * NTOT];  // q | k | v per row

// ---------------------------------------------------------------------------
// PTX helpers (compute_103-legal: cp.async / ldmatrix / mma.sync)
// ---------------------------------------------------------------------------
__device__ __forceinline__ u32 s2u(const void* p) {
    u32 a;
    asm("{ .reg .u64 t; cvta.to.shared.u64 t, %1; cvt.u32.u64 %0, t; }"
        : "=r"(a) : "l"(p));
    return a;
}
__device__ __forceinline__ void cpa16(u32 dst, const void* src) {
    asm volatile("cp.async.cg.shared.global [%0], [%1], 16;"
                 :: "r"(dst), "l"(src) : "memory");
}
#define CPA_COMMIT() asm volatile("cp.async.commit_group;" ::: "memory")
#define CPA_WAIT2()  asm volatile("cp.async.wait_group 2;" ::: "memory")

__device__ __forceinline__ void ldsm4(u32* r, u32 addr) {
    asm volatile("ldmatrix.sync.aligned.m8n8.x4.shared.b16 {%0,%1,%2,%3}, [%4];"
                 : "=r"(r[0]), "=r"(r[1]), "=r"(r[2]), "=r"(r[3]) : "r"(addr));
}
__device__ __forceinline__ void mma_bf16(float* d, const u32* a, const u32* b) {
    asm volatile(
        "mma.sync.aligned.m16n8k16.row.col.f32.bf16.bf16.f32 "
        "{%0,%1,%2,%3}, {%4,%5,%6,%7}, {%8,%9}, {%0,%1,%2,%3};"
        : "+f"(d[0]), "+f"(d[1]), "+f"(d[2]), "+f"(d[3])
        : "r"(a[0]), "r"(a[1]), "r"(a[2]), "r"(a[3]), "r"(b[0]), "r"(b[1]));
}

// ---------------------------------------------------------------------------
// Pack kernels: hi/lo bf16 split into the K-concat layout
// ---------------------------------------------------------------------------
__device__ __forceinline__ void split4(float4 v, __nv_bfloat162& h01, __nv_bfloat162& h23,
                                       __nv_bfloat162& l01, __nv_bfloat162& l23) {
    __nv_bfloat16 h0 = __float2bfloat16(v.x);
    __nv_bfloat16 h1 = __float2bfloat16(v.y);
    __nv_bfloat16 h2 = __float2bfloat16(v.z);
    __nv_bfloat16 h3 = __float2bfloat16(v.w);
    h01 = __halves2bfloat162(h0, h1);
    h23 = __halves2bfloat162(h2, h3);
    l01 = __halves2bfloat162(__float2bfloat16(v.x - __bfloat162float(h0)),
                             __float2bfloat16(v.y - __bfloat162float(h1)));
    l23 = __halves2bfloat162(__float2bfloat16(v.z - __bfloat162float(h2)),
                             __float2bfloat16(v.w - __bfloat162float(h3)));
}

__global__ void pack_x(const float4* __restrict__ x) {
    int i = blockIdx.x * blockDim.x + threadIdx.x;
    const int n4 = M_TOK * EDIM / 4;
    const int stride = gridDim.x * blockDim.x;
    __nv_bfloat162* out = (__nv_bfloat162*)g_ap;
    for (; i < n4; i += stride) {
        float4 v = x[i];
        __nv_bfloat162 h01, h23, l01, l23;
        split4(v, h01, h23, l01, l23);
        const int e0  = i * 4;
        const int row = e0 >> 10;
        const int col = e0 & 1023;
        const size_t base = ((size_t)row * KTOT + col) >> 1;
        out[base]        = h01;  out[base + 1]    = h23;   // hi
        out[base + 512]  = h01;  out[base + 513]  = h23;   // hi
        out[base + 1024] = l01;  out[base + 1025] = l23;   // lo
    }
}

__global__ void pack_w(const float4* __restrict__ Wq,
                       const float4* __restrict__ Wk,
                       const float4* __restrict__ Wv) {
    int i = blockIdx.x * blockDim.x + threadIdx.x;
    const int per = EDIM * EDIM / 4;
    const int n4 = 3 * per;
    const int stride = gridDim.x * blockDim.x;
    __nv_bfloat162* out = (__nv_bfloat162*)g_bp;
    for (; i < n4; i += stride) {
        const int z = i / per;
        const int r = i - z * per;
        float4 v = (z == 0 ? Wq : z == 1 ? Wk : Wv)[r];
        __nv_bfloat162 h01, h23, l01, l23;
        split4(v, h01, h23, l01, l23);
        const int e0  = r * 4;
        const int row = e0 >> 10;
        const int col = e0 & 1023;
        const size_t base = ((size_t)(z * EDIM + row) * KTOT + col) >> 1;
        out[base]        = h01;  out[base + 1]    = h23;   // hi
        out[base + 512]  = l01;  out[base + 513]  = l23;   // lo
        out[base + 1024] = h01;  out[base + 1025] = h23;   // hi
    }
}

__global__ void pack_bias(const float* __restrict__ bq,
                          const float* __restrict__ bk,
                          const float* __restrict__ bv) {
    int i = blockIdx.x * blockDim.x + threadIdx.x;
    if (i < NTOT) {
        const int z = i >> 10;
        g_bias[i] = (z == 0 ? bq : z == 1 ? bk : bv)[i & 1023];
    }
}

// ---------------------------------------------------------------------------
// bf16 mma.sync GEMM: C[m,n] = sum_k Apack[m,k]*Bpack[n,k] + bias[n]
// Tile 128x256x64, 256 threads (8 warps, 2Mx4N, 64x64 warp tiles),
// 4-stage cp.async pipeline, one barrier per k-iter.
// ---------------------------------------------------------------------------
#define GBM 128
#define GBN 256
#define GBK 64
#define NSTG 4
#define KIT (KTOT / GBK)          // 48
#define A_STG 16384               // 128 rows * 128B
#define B_STG 32768               // 256 rows * 128B
#define STG_BYTES (A_STG + B_STG) // 49152
#define SMEM_GEMM (NSTG * STG_BYTES + 128)

// swizzled smem byte offset for (row, 16B-chunk c) in a 128B-row tile
__device__ __forceinline__ u32 swz(int row, int c) {
    return (u32)(row * 128 + ((c ^ (row & 7)) << 4));
}

__device__ __forceinline__ void load_stage(u32 smb, int s, int kt,
                                           int row0, int col0, int tid) {
    const u32 aB = smb + s * STG_BYTES;
    const u32 bB = aB + A_STG;
    // A: 1024 chunks (128 rows x 8), 4 per thread
    #pragma unroll
    for (int j = 0; j < 4; j++) {
        const int ci = tid + j * 256;
        const int r = ci >> 3, c = ci & 7;
        cpa16(aB + swz(r, c),
              g_ap + (size_t)(row0 + r) * KTOT + kt * GBK + c * 8);
    }
    // B: 2048 chunks (256 rows x 8), 8 per thread
    #pragma unroll
    for (int j = 0; j < 8; j++) {
        const int ci = tid + j * 256;
        const int r = ci >> 3, c = ci & 7;
        cpa16(bB + swz(r, c),
              g_bp + (size_t)(col0 + r) * KTOT + kt * GBK + c * 8);
    }
}

__global__ void __launch_bounds__(256, 1)
qkv_mma_gemm()
{
    extern __shared__ char smraw[];
    const u32 smb = (s2u(smraw) + 127u) & ~127u;

    const int tid  = threadIdx.x;
    const int wid  = tid >> 5;
    const int lane = tid & 31;
    const int wm   = wid & 1;          // 0..1 -> 64 rows
    const int wn   = wid >> 1;         // 0..3 -> 64 cols
    const int row0 = blockIdx.y * GBM;
    const int col0 = blockIdx.x * GBN;

    float acc[4][8][4];
    #pragma unroll
    for (int i = 0; i < 4; i++)
        #pragma unroll
        for (int j = 0; j < 8; j++)
            #pragma unroll
            for (int k = 0; k < 4; k++) acc[i][j][k] = 0.f;

    // prologue: stages 0,1,2
    load_stage(smb, 0, 0, row0, col0, tid); CPA_COMMIT();
    load_stage(smb, 1, 1, row0, col0, tid); CPA_COMMIT();
    load_stage(smb, 2, 2, row0, col0, tid); CPA_COMMIT();

    for (int kt = 0; kt < KIT; kt++) {
        CPA_WAIT2();
        __syncthreads();

        // issue next stage immediately (slot was last read before the barrier)
        if (kt + 3 < KIT)
            load_stage(smb, (kt + 3) % NSTG, kt + 3, row0, col0, tid);
        CPA_COMMIT();

        const int s = kt % NSTG;
        const u32 aB = smb + s * STG_BYTES;
        const u32 bB = aB + A_STG;

        #pragma unroll
        for (int kk = 0; kk < 4; kk++) {
            u32 ra[4][4];
            #pragma unroll
            for (int mi = 0; mi < 4; mi++) {
                const int r = wm * 64 + mi * 16 + (lane & 15);
                const int c = kk * 2 + (lane >> 4);
                ldsm4(ra[mi], aB + swz(r, c));
            }
            u32 rb[4][4];
            #pragma unroll
            for (int ni = 0; ni < 4; ni++) {
                const int r = wn * 64 + ni * 16 + (lane & 7) + ((lane >> 4) << 3);
                const int c = kk * 2 + ((lane >> 3) & 1);
                ldsm4(rb[ni], bB + swz(r, c));
            }
            #pragma unroll
            for (int mi = 0; mi < 4; mi++)
                #pragma unroll
                for (int n8 = 0; n8 < 8; n8++)
                    mma_bf16(acc[mi][n8], ra[mi], &rb[n8 >> 1][(n8 & 1) * 2]);
        }
    }

    // epilogue: add bias, write g_qkv
    const int rbase = row0 + wm * 64;
    const int cbase = col0 + wn * 64;
    #pragma unroll
    for (int mi = 0; mi < 4; mi++) {
        const int r = rbase + mi * 16 + (lane >> 2);
        #pragma unroll
        for (int n8 = 0; n8 < 8; n8++) {
            const int c = cbase + n8 * 8 + (lane & 3) * 2;
            const float b0 = g_bias[c], b1 = g_bias[c + 1];
            float2 v0 = make_float2(acc[mi][n8][0] + b0, acc[mi][n8][1] + b1);
            float2 v1 = make_float2(acc[mi][n8][2] + b0, acc[mi][n8][3] + b1);
            *(float2*)&g_qkv[(size_t)r * NTOT + c]       = v0;
            *(float2*)&g_qkv[(size_t)(r + 8) * NTOT + c] = v1;
        }
    }
}

// ---------------------------------------------------------------------------
// Per-token head-head attention, register-split version.
// 128 threads / 4 tokens per block; 32 threads per token = (head, D-half).
// Score halves combined via shfl.xor(16). Mask-before-softmax semantics.
// ---------------------------------------------------------------------------
__global__ __launch_bounds__(128)
void attn_kernel(const float* __restrict__ mask, float* __restrict__ out)
{
    __shared__ float ks[4 * HEADS * DH];   // 16 KB
    __shared__ float vs[4 * HEADS * DH];   // 16 KB
    __shared__ float ms[HEADS * HEADS];    // 1 KB

    const int tid = threadIdx.x;
    const size_t tok0 = (size_t)blockIdx.x * 4;

    for (int i = tid; i < HEADS * HEADS; i += 128) ms[i] = mask[i];

    float4* ks4 = (float4*)ks;
    float4* vs4 = (float4*)vs;
    #pragma unroll
    for (int tt = 0; tt < 4; tt++) {
        const float4* kg = (const float4*)(g_qkv + (tok0 + tt) * NTOT + EDIM);
        const float4* vg = (const float4*)(g_qkv + (tok0 + tt) * NTOT + 2 * EDIM);
        #pragma unroll
        for (int j = 0; j < 2; j++) {
            const int idx = tid + j * 128;
            ks4[tt * 256 + idx] = kg[idx];
            vs4[tt * 256 + idx] = vg[idx];
        }
    }
    __syncthreads();

    const int t    = tid >> 5;       // token (one warp per token)
    const int lane = tid & 31;
    const int h    = lane & 15;      // head
    const int half = lane >> 4;      // D-half (0: dims 0-31, 1: dims 32-63)

    // q half-row into registers (8 float4 = 32 floats)
    float4 qv[8];
    const float4* qp = (const float4*)(g_qkv + (tok0 + t) * NTOT + h * DH + half * 32);
    #pragma unroll
    for (int i = 0; i < 8; i++) qv[i] = qp[i];

    // scores: partial dot over this half, combine with partner via shfl
    float s[16];
    #pragma unroll
    for (int g = 0; g < 16; g++) {
        const float4* kr = (const float4*)(ks + (t * HEADS + g) * DH + half * 32);
        float ax = 0.f, ay = 0.f, az = 0.f, aw = 0.f;
        #pragma unroll
        for (int i = 0; i < 8; i++) {
            float4 kv = kr[i];
            ax += qv[i].x * kv.x; ay += qv[i].y * kv.y;
            az += qv[i].z * kv.z; aw += qv[i].w * kv.w;
        }
        float p = (ax + ay) + (az + aw);
        p += __shfl_xor_sync(0xFFFFFFFFu, p, 16);
        s[g] = p * ms[h * HEADS + g];
    }

    // softmax over g (masked-to-zero entries included, like the reference)
    float m = s[0];
    #pragma unroll
    for (int g = 1; g < 16; g++) m = fmaxf(m, s[g]);
    float denom = 0.f;
    #pragma unroll
    for (int g = 0; g < 16; g++) { s[g] = expf(s[g] - m); denom += s[g]; }
    const float inv = 1.f / denom;

    // out half-row = sum_g p_g * v[g][half]
    float4 o[8];
    #pragma unroll
    for (int i = 0; i < 8; i++) o[i] = make_float4(0.f, 0.f, 0.f, 0.f);
    #pragma unroll
    for (int g = 0; g < 16; g++) {
        const float p = s[g] * inv;
        const float4* vr = (const float4*)(vs + (t * HEADS + g) * DH + half * 32);
        #pragma unroll
        for (int i = 0; i < 8; i++) {
            float4 vv = vr[i];
            o[i].x += p * vv.x; o[i].y += p * vv.y;
            o[i].z += p * vv.z; o[i].w += p * vv.w;
        }
    }

    float4* op = (float4*)(out + (tok0 + t) * EDIM + h * DH + half * 32);
    #pragma unroll
    for (int i = 0; i < 8; i++) op[i] = o[i];
}

// ---------------------------------------------------------------------------
// Launch. Inputs: x, sparsity_pattern, Wq, bq, Wk, bk, Wv, bv
// ---------------------------------------------------------------------------
extern "C" void kernel_launch(void* const* d_in, const int* in_sizes, int n_in,
                              void* d_out, int out_size)
{
    (void)in_sizes; (void)n_in; (void)out_size;
    const float* x  = (const float*)d_in[0];
    const float* sp = (const float*)d_in[1];
    const float* Wq = (const float*)d_in[2];
    const float* bq = (const float*)d_in[3];
    const float* Wk = (const float*)d_in[4];
    const float* bk = (const float*)d_in[5];
    const float* Wv = (const float*)d_in[6];
    const float* bv = (const float*)d_in[7];
    float* out = (float*)d_out;

    pack_x<<<4096, 256>>>((const float4*)x);
    pack_w<<<1536, 256>>>((const float4*)Wq, (const float4*)Wk, (const float4*)Wv);
    pack_bias<<<12, 256>>>(bq, bk, bv);

    cudaFuncSetAttribute(qkv_mma_gemm,
                         cudaFuncAttributeMaxDynamicSharedMemorySize, SMEM_GEMM);
    dim3 grid(NTOT / GBN, M_TOK / GBM);    // (12, 128)
    qkv_mma_gemm<<<grid, 256, SMEM_GEMM>>>();

    attn_kernel<<<M_TOK / 4, 128>>>(sp, out);
}